// round 6
// baseline (speedup 1.0000x reference)
#include <cuda_runtime.h>
#include <cuda_fp16.h>
#include <cstdint>

#define Bn 8192
#define En 16
#define Zn 256
#define Hn 1024
#define Un 256
#define TM 64
#define MAXT 144
#define NT 512
#define NC 128
#define KC 64
#define LDA 264                  // A smem row stride (halves)
#define LDB 72                   // B smem row stride (halves)
#define BPART (128*LDB*2)        // 18432 B per buffer

// smem byte offsets
#define OASH 0
#define OA2H (TM*LDA*2)          // 33792
#define OBS  (2*TM*LDA*2)        // 67584
#define SMEM_DYN (OBS + 4*BPART) // 141312

// ---------------- device scratch ----------------
__device__ int g_perm[Bn];
__device__ int g_te[MAXT], g_ts[MAXT], g_tr[MAXT];
__device__ int g_ntiles;
__device__ __half g_Wzh[(size_t)En*Zn*Zn];
__device__ __half g_Whh[(size_t)En*Hn*Zn];
__device__ __half g_Wuh[(size_t)En*Un*Un];

// ---------------- helpers ----------------
__device__ __forceinline__ uint32_t s2u(const void* p) {
    uint32_t a;
    asm("{ .reg .u64 t; cvta.to.shared.u64 t, %1; cvt.u32.u64 %0, t; }" : "=r"(a) : "l"(p));
    return a;
}
__device__ __forceinline__ void cpa16(uint32_t dst, const void* src) {
    asm volatile("cp.async.ca.shared.global [%0], [%1], 16;" :: "r"(dst), "l"(src));
}
__device__ __forceinline__ void cpa_commit() { asm volatile("cp.async.commit_group;" ::: "memory"); }
template<int N> __device__ __forceinline__ void cpa_wait() {
    asm volatile("cp.async.wait_group %0;" :: "n"(N) : "memory");
}
__device__ __forceinline__ void ldm4(uint32_t r[4], uint32_t addr) {
    asm volatile("ldmatrix.sync.aligned.m8n8.x4.shared.b16 {%0,%1,%2,%3}, [%4];"
                 : "=r"(r[0]), "=r"(r[1]), "=r"(r[2]), "=r"(r[3]) : "r"(addr));
}
__device__ __forceinline__ void mma16816(float c[4], const uint32_t a[4], uint32_t b0, uint32_t b1) {
    asm volatile("mma.sync.aligned.m16n8k16.row.col.f32.f16.f16.f32 "
                 "{%0,%1,%2,%3}, {%4,%5,%6,%7}, {%8,%9}, {%0,%1,%2,%3};"
                 : "+f"(c[0]), "+f"(c[1]), "+f"(c[2]), "+f"(c[3])
                 : "r"(a[0]), "r"(a[1]), "r"(a[2]), "r"(a[3]), "r"(b0), "r"(b1));
}

// ---------------- fused pre-pass: weight cvt (blocks 0..PREBLK-1) + setup (block PREBLK) ----------------
#define NWz4 (En*Zn*Zn/4)      // 262144
#define NWh4 (En*Hn*Zn/4)      // 1048576
#define NWu4 (En*Un*Un/4)      // 262144
#define NW4  (NWz4+NWh4+NWu4)  // 1572864
#define PREBLK (NW4/NT)        // 3072

__global__ __launch_bounds__(NT) void k_pre(const int* __restrict__ rng,
                                            const float* __restrict__ Wz,
                                            const float* __restrict__ Wh,
                                            const float* __restrict__ Wu) {
    if (blockIdx.x == PREBLK) {
        // ---- expert bucketing: warp-aggregated hist + scan + scatter ----
        __shared__ int sc[En], soff[En], scur[En];
        const int tid = threadIdx.x, lane = tid & 31;
        if (tid < En) { sc[tid] = 0; scur[tid] = 0; }
        __syncthreads();
        for (int i = tid; i < Bn; i += NT) {
            int e = rng[i];
            unsigned m = __match_any_sync(0xffffffffu, e);
            if (lane == __ffs(m) - 1) atomicAdd(&sc[e], __popc(m));
        }
        __syncthreads();
        if (tid == 0) {
            int acc = 0, nt = 0;
            for (int e = 0; e < En; e++) {
                soff[e] = acc;
                int c = sc[e];
                for (int s = 0; s < c; s += TM) {
                    g_te[nt] = e;
                    g_ts[nt] = acc + s;
                    g_tr[nt] = (c - s) < TM ? (c - s) : TM;
                    nt++;
                }
                acc += c;
            }
            g_ntiles = nt;
        }
        __syncthreads();
        for (int i = tid; i < Bn; i += NT) {
            int e = rng[i];
            unsigned m = __match_any_sync(0xffffffffu, e);
            int leader = __ffs(m) - 1;
            int rank = __popc(m & ((1u << lane) - 1u));
            int base = 0;
            if (lane == leader) base = atomicAdd(&scur[e], __popc(m));
            base = __shfl_sync(0xffffffffu, base, leader);
            g_perm[soff[e] + base + rank] = i;
        }
        return;
    }
    // ---- weight fp32 -> fp16 (hi only) ----
    int i = blockIdx.x * NT + threadIdx.x;
    const float* src; __half* dh; int j = i;
    if (j < NWz4)                { src = Wz; dh = g_Wzh; }
    else if ((j -= NWz4) < NWh4) { src = Wh; dh = g_Whh; }
    else { j -= NWh4;              src = Wu; dh = g_Wuh; }
    float4 v = __ldg((const float4*)src + j);
    union { __half2 h[2]; uint2 q; } P;
    P.h[0] = __floats2half2_rn(v.x, v.y);
    P.h[1] = __floats2half2_rn(v.z, v.w);
    ((uint2*)dh)[j] = P.q;
}

// ---------------- A staging: gathered fp32 rows -> fp16 smem ----------------
__device__ __forceinline__ void stage_a32(char* smc, int off, const float* __restrict__ g,
                                          const int* ss, int tid) {
#pragma unroll
    for (int i = tid; i < TM * 32; i += NT) {
        int r = i >> 5, c = (i & 31) << 3;
        int s = ss[r];
        uint4 q = make_uint4(0u, 0u, 0u, 0u);
        if (s >= 0) {
            const float4 v0 = __ldg((const float4*)(g + (size_t)s * 256 + c));
            const float4 v1 = __ldg((const float4*)(g + (size_t)s * 256 + c + 4));
            union { __half2 h[4]; uint4 u; } P;
            P.h[0] = __floats2half2_rn(v0.x, v0.y);
            P.h[1] = __floats2half2_rn(v0.z, v0.w);
            P.h[2] = __floats2half2_rn(v1.x, v1.y);
            P.h[3] = __floats2half2_rn(v1.z, v1.w);
            q = P.u;
        }
        *(uint4*)(smc + off + (uint32_t)(r * LDA + c) * 2) = q;
    }
}

// B chunk: 128 rows x 64 halves via cp.async
__device__ __forceinline__ void stage_b(uint32_t bh, const __half* __restrict__ gh, int kc, int tid) {
    for (int i = tid; i < 128 * 8; i += NT) {
        int r = i >> 3, c = (i & 7) << 3;
        cpa16(bh + (uint32_t)(r * LDB + c) * 2, gh + (size_t)r * 256 + kc * KC + c);
    }
}

// ---------------- GEMM: one 64x128 output chunk, fp16 1-product ----------------
// 4 B-buffers, chunk kc -> buffer kc (no ring reuse within a call; next call's
// buffer-0 stage only overlaps tail compute on buffer 3 -> race-free).
__device__ __forceinline__ void gemm_nc(uint32_t aH, uint32_t obs,
                                        const __half* __restrict__ gB,
                                        float c[4][4], int tid) {
    const int lane = tid & 31, warp = tid >> 5;
    const int wm = warp >> 2, wn = warp & 3;
    const int lrow = (lane & 7) + ((lane >> 3) & 1) * 8;
    const int lk8  = (lane >> 4) * 8;

#pragma unroll
    for (int nt = 0; nt < 4; nt++)
#pragma unroll
        for (int j = 0; j < 4; j++) c[nt][j] = 0.f;

    stage_b(obs, gB, 0, tid);
    cpa_commit();

#pragma unroll
    for (int kc = 0; kc < 4; kc++) {
        if (kc < 3) {
            stage_b(obs + (uint32_t)(kc + 1) * BPART, gB, kc + 1, tid);
            cpa_commit();
            cpa_wait<1>();
        } else {
            cpa_wait<0>();
        }
        __syncthreads();

        const uint32_t bH = obs + (uint32_t)kc * BPART;
#pragma unroll
        for (int k16 = 0; k16 < 4; k16++) {
            const int ka = kc * KC + k16 * 16;
            uint32_t ah[4];
            ldm4(ah, aH + (uint32_t)((wm * 16 + lrow) * LDA + ka + lk8) * 2);
            uint32_t bf[2][4];
#pragma unroll
            for (int ng = 0; ng < 2; ng++)
                ldm4(bf[ng], bH + (uint32_t)((wn * 32 + ng * 16 + lrow) * LDB + k16 * 16 + lk8) * 2);
#pragma unroll
            for (int nt = 0; nt < 4; nt++) {
                const int ng = nt >> 1, sel = nt & 1;
                mma16816(c[nt], ah, bf[ng][sel], bf[ng][sel + 2]);
            }
        }
    }
}

// ---------------- fused MoE kernel ----------------
__global__ __launch_bounds__(NT, 1)
void k_moe(const float* __restrict__ z, const float* __restrict__ u,
           const float* __restrict__ bz, const float* __restrict__ bhb,
           float* __restrict__ out) {
    const int bt = blockIdx.x;
    if (bt >= g_ntiles) return;
    const int e = g_te[bt], start = g_ts[bt], rows = g_tr[bt];
    const int tid = threadIdx.x, lane = tid & 31, warp = tid >> 5;
    const int wm = warp >> 2, wn = warp & 3;
    const int t4 = lane >> 2, t2 = (lane & 3) * 2;

    extern __shared__ char smc[];
    const uint32_t sm0 = s2u(smc);
    const uint32_t aSH = sm0 + OASH, a2H = sm0 + OA2H, obs = sm0 + OBS;

    __shared__ int ss[TM];
    if (tid < TM) ss[tid] = (tid < rows) ? g_perm[start + tid] : -1;
    __syncthreads();

    stage_a32(smc, OASH, z, ss, tid);

    float c[4][4];

    // ---- GEMM1: a = z @ Wz^T + bz -> a2H smem (fp16) ----
    {
        const __half* Bh = g_Wzh + (size_t)e * Zn * Zn;
        for (int nc = 0; nc < Zn / NC; nc++) {
            gemm_nc(aSH, obs, Bh + (size_t)nc * NC * Zn, c, tid);
            const float* bzp = bz + (size_t)e * Zn + nc * NC;
            const int r0 = wm * 16 + t4;
#pragma unroll
            for (int nt = 0; nt < 4; nt++) {
                const int col = wn * 32 + nt * 8 + t2;
                const float2 bb = *(const float2*)(bzp + col);
                uint32_t o = (uint32_t)(r0 * LDA + nc * NC + col) * 2;
                *(__half2*)(smc + OA2H + o) = __floats2half2_rn(c[nt][0] + bb.x, c[nt][1] + bb.y);
                o = (uint32_t)((r0 + 8) * LDA + nc * NC + col) * 2;
                *(__half2*)(smc + OA2H + o) = __floats2half2_rn(c[nt][2] + bb.x, c[nt][3] + bb.y);
            }
        }
    }
    __syncthreads();   // all warps done with aSH (GEMM1 A) and a2H writes visible

    // stage u into aSH
    stage_a32(smc, OASH, u, ss, tid);

    // ---- GEMM2: h = relu(a @ Wh^T + bh) -> out ----
    {
        const __half* Bh = g_Whh + (size_t)e * Hn * Zn;
        for (int nc = 0; nc < Hn / NC; nc++) {
            gemm_nc(a2H, obs, Bh + (size_t)nc * NC * Zn, c, tid);
            const float* bhp = bhb + (size_t)e * Hn + nc * NC;
            const int r0 = wm * 16 + t4;
            const int s0 = ss[r0], s1 = ss[r0 + 8];
#pragma unroll
            for (int nt = 0; nt < 4; nt++) {
                const int col = wn * 32 + nt * 8 + t2;
                const float2 bb = *(const float2*)(bhp + col);
                if (s0 >= 0) {
                    float2 o;
                    o.x = fmaxf(c[nt][0] + bb.x, 0.f);
                    o.y = fmaxf(c[nt][1] + bb.y, 0.f);
                    *(float2*)(out + (size_t)s0 * Hn + nc * NC + col) = o;
                }
                if (s1 >= 0) {
                    float2 o;
                    o.x = fmaxf(c[nt][2] + bb.x, 0.f);
                    o.y = fmaxf(c[nt][3] + bb.y, 0.f);
                    *(float2*)(out + (size_t)s1 * Hn + nc * NC + col) = o;
                }
            }
        }
    }

    // ---- GEMM3: v = u @ Wu^T -> out + Bn*Hn ----
    {
        const __half* Bh = g_Wuh + (size_t)e * Un * Un;
        float* outv = out + (size_t)Bn * Hn;
        for (int nc = 0; nc < Un / NC; nc++) {
            gemm_nc(aSH, obs, Bh + (size_t)nc * NC * Zn, c, tid);
            const int r0 = wm * 16 + t4;
            const int s0 = ss[r0], s1 = ss[r0 + 8];
#pragma unroll
            for (int nt = 0; nt < 4; nt++) {
                const int col = wn * 32 + nt * 8 + t2;
                if (s0 >= 0) {
                    float2 o; o.x = c[nt][0]; o.y = c[nt][1];
                    *(float2*)(outv + (size_t)s0 * Un + nc * NC + col) = o;
                }
                if (s1 >= 0) {
                    float2 o; o.x = c[nt][2]; o.y = c[nt][3];
                    *(float2*)(outv + (size_t)s1 * Un + nc * NC + col) = o;
                }
            }
        }
    }
}

// ---------------- launcher ----------------
extern "C" void kernel_launch(void* const* d_in, const int* in_sizes, int n_in,
                              void* d_out, int out_size) {
    (void)in_sizes; (void)n_in; (void)out_size;
    const float* z   = (const float*)d_in[0];
    const float* u   = (const float*)d_in[1];
    const int*   rng = (const int*)d_in[2];
    const float* Wz  = (const float*)d_in[3];
    const float* bz  = (const float*)d_in[4];
    const float* Wh  = (const float*)d_in[5];
    const float* bh  = (const float*)d_in[6];
    const float* Wu  = (const float*)d_in[7];
    float* out = (float*)d_out;

    cudaFuncSetAttribute(k_moe, cudaFuncAttributeMaxDynamicSharedMemorySize, SMEM_DYN);

    k_pre<<<PREBLK + 1, NT>>>(rng, Wz, Wh, Wu);
    k_moe<<<MAXT, NT, SMEM_DYN>>>(z, u, bz, bh, out);
}

// round 7
// speedup vs baseline: 1.1196x; 1.1196x over previous
#include <cuda_runtime.h>
#include <cuda_fp16.h>
#include <cstdint>

#define Bn 8192
#define En 16
#define Zn 256
#define Hn 1024
#define Un 256
#define TM 64
#define MAXT 144
#define NT 512
#define NC 256                   // N chunk (per gemm call)
#define KC 64                    // K chunk
#define LDA 264                  // A smem row stride (halves)
#define LDB 72                   // B smem row stride (halves)
#define BPART (NC*LDB*2)         // 36864 B per buffer

// smem byte offsets
#define OASH 0
#define OA2H (TM*LDA*2)          // 33792
#define OBS  (2*TM*LDA*2)        // 67584
#define SMEM_DYN (OBS + 3*BPART) // 178176

// ---------------- device scratch ----------------
__device__ int g_perm[Bn];
__device__ int g_te[MAXT], g_ts[MAXT], g_tr[MAXT];
__device__ int g_ntiles;
__device__ __half g_Wzh[(size_t)En*Zn*Zn];
__device__ __half g_Whh[(size_t)En*Hn*Zn];
__device__ __half g_Wuh[(size_t)En*Un*Un];

// ---------------- helpers ----------------
__device__ __forceinline__ uint32_t s2u(const void* p) {
    uint32_t a;
    asm("{ .reg .u64 t; cvta.to.shared.u64 t, %1; cvt.u32.u64 %0, t; }" : "=r"(a) : "l"(p));
    return a;
}
__device__ __forceinline__ void cpa16(uint32_t dst, const void* src) {
    asm volatile("cp.async.ca.shared.global [%0], [%1], 16;" :: "r"(dst), "l"(src));
}
__device__ __forceinline__ void cpa_commit() { asm volatile("cp.async.commit_group;" ::: "memory"); }
template<int N> __device__ __forceinline__ void cpa_wait() {
    asm volatile("cp.async.wait_group %0;" :: "n"(N) : "memory");
}
__device__ __forceinline__ void ldm4(uint32_t r[4], uint32_t addr) {
    asm volatile("ldmatrix.sync.aligned.m8n8.x4.shared.b16 {%0,%1,%2,%3}, [%4];"
                 : "=r"(r[0]), "=r"(r[1]), "=r"(r[2]), "=r"(r[3]) : "r"(addr));
}
__device__ __forceinline__ void mma16816(float c[4], const uint32_t a[4], uint32_t b0, uint32_t b1) {
    asm volatile("mma.sync.aligned.m16n8k16.row.col.f32.f16.f16.f32 "
                 "{%0,%1,%2,%3}, {%4,%5,%6,%7}, {%8,%9}, {%0,%1,%2,%3};"
                 : "+f"(c[0]), "+f"(c[1]), "+f"(c[2]), "+f"(c[3])
                 : "r"(a[0]), "r"(a[1]), "r"(a[2]), "r"(a[3]), "r"(b0), "r"(b1));
}

// ---------------- fused pre-pass: weight cvt + setup ----------------
#define NWz4 (En*Zn*Zn/4)
#define NWh4 (En*Hn*Zn/4)
#define NWu4 (En*Un*Un/4)
#define NW4  (NWz4+NWh4+NWu4)
#define PREBLK (NW4/NT)          // 3072

__global__ __launch_bounds__(NT) void k_pre(const int* __restrict__ rng,
                                            const float* __restrict__ Wz,
                                            const float* __restrict__ Wh,
                                            const float* __restrict__ Wu) {
    if (blockIdx.x == PREBLK) {
        __shared__ int sc[En], soff[En], scur[En];
        const int tid = threadIdx.x, lane = tid & 31;
        if (tid < En) { sc[tid] = 0; scur[tid] = 0; }
        __syncthreads();
        for (int i = tid; i < Bn; i += NT) {
            int e = rng[i];
            unsigned m = __match_any_sync(0xffffffffu, e);
            if (lane == __ffs(m) - 1) atomicAdd(&sc[e], __popc(m));
        }
        __syncthreads();
        if (tid == 0) {
            int acc = 0, nt = 0;
            for (int e = 0; e < En; e++) {
                soff[e] = acc;
                int c = sc[e];
                for (int s = 0; s < c; s += TM) {
                    g_te[nt] = e;
                    g_ts[nt] = acc + s;
                    g_tr[nt] = (c - s) < TM ? (c - s) : TM;
                    nt++;
                }
                acc += c;
            }
            g_ntiles = nt;
        }
        __syncthreads();
        for (int i = tid; i < Bn; i += NT) {
            int e = rng[i];
            unsigned m = __match_any_sync(0xffffffffu, e);
            int leader = __ffs(m) - 1;
            int rank = __popc(m & ((1u << lane) - 1u));
            int base = 0;
            if (lane == leader) base = atomicAdd(&scur[e], __popc(m));
            base = __shfl_sync(0xffffffffu, base, leader);
            g_perm[soff[e] + base + rank] = i;
        }
        return;
    }
    int i = blockIdx.x * NT + threadIdx.x;
    const float* src; __half* dh; int j = i;
    if (j < NWz4)                { src = Wz; dh = g_Wzh; }
    else if ((j -= NWz4) < NWh4) { src = Wh; dh = g_Whh; }
    else { j -= NWh4;              src = Wu; dh = g_Wuh; }
    float4 v = __ldg((const float4*)src + j);
    union { __half2 h[2]; uint2 q; } P;
    P.h[0] = __floats2half2_rn(v.x, v.y);
    P.h[1] = __floats2half2_rn(v.z, v.w);
    ((uint2*)dh)[j] = P.q;
}

// ---------------- A staging: gathered fp32 rows -> fp16 smem ----------------
__device__ __forceinline__ void stage_a32(char* smc, int off, const float* __restrict__ g,
                                          const int* ss, int tid) {
#pragma unroll
    for (int i = tid; i < TM * 32; i += NT) {
        int r = i >> 5, c = (i & 31) << 3;
        int s = ss[r];
        uint4 q = make_uint4(0u, 0u, 0u, 0u);
        if (s >= 0) {
            const float4 v0 = __ldg((const float4*)(g + (size_t)s * 256 + c));
            const float4 v1 = __ldg((const float4*)(g + (size_t)s * 256 + c + 4));
            union { __half2 h[4]; uint4 u; } P;
            P.h[0] = __floats2half2_rn(v0.x, v0.y);
            P.h[1] = __floats2half2_rn(v0.z, v0.w);
            P.h[2] = __floats2half2_rn(v1.x, v1.y);
            P.h[3] = __floats2half2_rn(v1.z, v1.w);
            q = P.u;
        }
        *(uint4*)(smc + off + (uint32_t)(r * LDA + c) * 2) = q;
    }
}

// B chunk: NC rows x 64 halves via cp.async
__device__ __forceinline__ void stage_b(uint32_t bh, const __half* __restrict__ gh, int kc, int tid) {
#pragma unroll
    for (int i = tid; i < NC * 8; i += NT) {
        int r = i >> 3, c = (i & 7) << 3;
        cpa16(bh + (uint32_t)(r * LDB + c) * 2, gh + (size_t)r * 256 + kc * KC + c);
    }
}

// ---------------- GEMM: one 64x256 output chunk, fp16 ----------------
// Warp tile 32x32; warps: wm = warp>>3 (2), wn = warp&7 (8).
// 3-buffer B ring rotating ACROSS calls via 'rot' (race-free: writer lands
// 2-mod-3 behind the active reader; one barrier per K-chunk).
__device__ __forceinline__ void gemm_nc(uint32_t aH, uint32_t obs, int rot,
                                        const __half* __restrict__ gB,
                                        float c[2][4][4], int tid) {
    const int lane = tid & 31, warp = tid >> 5;
    const int wm = warp >> 3, wn = warp & 7;
    const int lrow = (lane & 7) + ((lane >> 3) & 1) * 8;
    const int lk8  = (lane >> 4) * 8;

#pragma unroll
    for (int mt = 0; mt < 2; mt++)
#pragma unroll
        for (int nt = 0; nt < 4; nt++)
#pragma unroll
            for (int j = 0; j < 4; j++) c[mt][nt][j] = 0.f;

    stage_b(obs + (uint32_t)(rot % 3) * BPART, gB, 0, tid);
    cpa_commit();

#pragma unroll
    for (int kc = 0; kc < 4; kc++) {
        if (kc < 3) {
            stage_b(obs + (uint32_t)((rot + kc + 1) % 3) * BPART, gB, kc + 1, tid);
            cpa_commit();
            cpa_wait<1>();
        } else {
            cpa_wait<0>();
        }
        __syncthreads();

        const uint32_t bH = obs + (uint32_t)((rot + kc) % 3) * BPART;
#pragma unroll
        for (int k16 = 0; k16 < 4; k16++) {
            const int ka = kc * KC + k16 * 16;
            uint32_t ah[2][4];
#pragma unroll
            for (int mt = 0; mt < 2; mt++)
                ldm4(ah[mt], aH + (uint32_t)((wm * 32 + mt * 16 + lrow) * LDA + ka + lk8) * 2);
            uint32_t bf[2][4];
#pragma unroll
            for (int ng = 0; ng < 2; ng++)
                ldm4(bf[ng], bH + (uint32_t)((wn * 32 + ng * 16 + lrow) * LDB + k16 * 16 + lk8) * 2);
#pragma unroll
            for (int mt = 0; mt < 2; mt++)
#pragma unroll
                for (int nt = 0; nt < 4; nt++) {
                    const int ng = nt >> 1, sel = nt & 1;
                    mma16816(c[mt][nt], ah[mt], bf[ng][sel], bf[ng][sel + 2]);
                }
        }
    }
}

// ---------------- fused MoE kernel ----------------
__global__ __launch_bounds__(NT, 1)
void k_moe(const float* __restrict__ z, const float* __restrict__ u,
           const float* __restrict__ bz, const float* __restrict__ bhb,
           float* __restrict__ out) {
    const int bt = blockIdx.x;
    if (bt >= g_ntiles) return;
    const int e = g_te[bt], start = g_ts[bt], rows = g_tr[bt];
    const int tid = threadIdx.x, lane = tid & 31, warp = tid >> 5;
    const int wm = warp >> 3, wn = warp & 7;
    const int t4 = lane >> 2, t2 = (lane & 3) * 2;

    extern __shared__ char smc[];
    const uint32_t sm0 = s2u(smc);
    const uint32_t aSH = sm0 + OASH, a2H = sm0 + OA2H, obs = sm0 + OBS;

    __shared__ int ss[TM];
    if (tid < TM) ss[tid] = (tid < rows) ? g_perm[start + tid] : -1;
    __syncthreads();

    stage_a32(smc, OASH, z, ss, tid);

    float c[2][4][4];
    int rot = 0;   // ring rotation: +4 chunks per call == +1 mod 3

    // ---- GEMM1: a = z @ Wz^T + bz -> a2H smem (fp16), single N=256 chunk ----
    {
        const __half* Bh = g_Wzh + (size_t)e * Zn * Zn;
        gemm_nc(aSH, obs, rot, Bh, c, tid); rot++;
        const float* bzp = bz + (size_t)e * Zn;
#pragma unroll
        for (int mt = 0; mt < 2; mt++) {
            const int r0 = wm * 32 + mt * 16 + t4;
#pragma unroll
            for (int nt = 0; nt < 4; nt++) {
                const int col = wn * 32 + nt * 8 + t2;
                const float2 bb = *(const float2*)(bzp + col);
                uint32_t o = (uint32_t)(r0 * LDA + col) * 2;
                *(__half2*)(smc + OA2H + o) = __floats2half2_rn(c[mt][nt][0] + bb.x, c[mt][nt][1] + bb.y);
                o = (uint32_t)((r0 + 8) * LDA + col) * 2;
                *(__half2*)(smc + OA2H + o) = __floats2half2_rn(c[mt][nt][2] + bb.x, c[mt][nt][3] + bb.y);
            }
        }
    }
    __syncthreads();   // aSH free for u; a2H writes visible before GEMM2's internal barrier

    // stage u into aSH
    stage_a32(smc, OASH, u, ss, tid);

    // ---- GEMM2: h = relu(a @ Wh^T + bh) -> out, 4 chunks of N=256 ----
    {
        const __half* Bh = g_Whh + (size_t)e * Hn * Zn;
        for (int nc = 0; nc < Hn / NC; nc++) {
            gemm_nc(a2H, obs, rot, Bh + (size_t)nc * NC * Zn, c, tid); rot++;
            const float* bhp = bhb + (size_t)e * Hn + nc * NC;
#pragma unroll
            for (int mt = 0; mt < 2; mt++) {
                const int r0 = wm * 32 + mt * 16 + t4;
                const int s0 = ss[r0], s1 = ss[r0 + 8];
#pragma unroll
                for (int nt = 0; nt < 4; nt++) {
                    const int col = wn * 32 + nt * 8 + t2;
                    const float2 bb = *(const float2*)(bhp + col);
                    if (s0 >= 0) {
                        float2 o;
                        o.x = fmaxf(c[mt][nt][0] + bb.x, 0.f);
                        o.y = fmaxf(c[mt][nt][1] + bb.y, 0.f);
                        *(float2*)(out + (size_t)s0 * Hn + nc * NC + col) = o;
                    }
                    if (s1 >= 0) {
                        float2 o;
                        o.x = fmaxf(c[mt][nt][2] + bb.x, 0.f);
                        o.y = fmaxf(c[mt][nt][3] + bb.y, 0.f);
                        *(float2*)(out + (size_t)s1 * Hn + nc * NC + col) = o;
                    }
                }
            }
        }
    }

    // ---- GEMM3: v = u @ Wu^T -> out + Bn*Hn, single N=256 chunk ----
    {
        const __half* Bh = g_Wuh + (size_t)e * Un * Un;
        float* outv = out + (size_t)Bn * Hn;
        gemm_nc(aSH, obs, rot, Bh, c, tid); rot++;
#pragma unroll
        for (int mt = 0; mt < 2; mt++) {
            const int r0 = wm * 32 + mt * 16 + t4;
            const int s0 = ss[r0], s1 = ss[r0 + 8];
#pragma unroll
            for (int nt = 0; nt < 4; nt++) {
                const int col = wn * 32 + nt * 8 + t2;
                if (s0 >= 0) {
                    float2 o; o.x = c[mt][nt][0]; o.y = c[mt][nt][1];
                    *(float2*)(outv + (size_t)s0 * Un + col) = o;
                }
                if (s1 >= 0) {
                    float2 o; o.x = c[mt][nt][2]; o.y = c[mt][nt][3];
                    *(float2*)(outv + (size_t)s1 * Un + col) = o;
                }
            }
        }
    }
}

// ---------------- launcher ----------------
extern "C" void kernel_launch(void* const* d_in, const int* in_sizes, int n_in,
                              void* d_out, int out_size) {
    (void)in_sizes; (void)n_in; (void)out_size;
    const float* z   = (const float*)d_in[0];
    const float* u   = (const float*)d_in[1];
    const int*   rng = (const int*)d_in[2];
    const float* Wz  = (const float*)d_in[3];
    const float* bz  = (const float*)d_in[4];
    const float* Wh  = (const float*)d_in[5];
    const float* bh  = (const float*)d_in[6];
    const float* Wu  = (const float*)d_in[7];
    float* out = (float*)d_out;

    cudaFuncSetAttribute(k_moe, cudaFuncAttributeMaxDynamicSharedMemorySize, SMEM_DYN);

    k_pre<<<PREBLK + 1, NT>>>(rng, Wz, Wh, Wu);
    k_moe<<<MAXT, NT, SMEM_DYN>>>(z, u, bz, bh, out);
}